// round 1
// baseline (speedup 1.0000x reference)
#include <cuda_runtime.h>

#define N_VEC   65536
#define CDIM    64
#define KCODES  1024
#define HWDIM   1024
#define BM      128     // rows per block
#define BK      64      // codes per chunk
#define NCHUNK  (KCODES / BK)

__device__ float d_hn[KCODES];   // 0.5 * ||c_k||^2

__global__ void hn_kernel(const float* __restrict__ cb) {
    int k = blockIdx.x * blockDim.x + threadIdx.x;
    if (k < KCODES) {
        const float4* row = reinterpret_cast<const float4*>(cb + k * CDIM);
        float s = 0.f;
        #pragma unroll
        for (int i = 0; i < CDIM / 4; ++i) {
            float4 v = __ldg(&row[i]);
            s += v.x * v.x + v.y * v.y + v.z * v.z + v.w * v.w;
        }
        d_hn[k] = 0.5f * s;
    }
}

static __forceinline__ __device__ unsigned long long pack2(float a, float b) {
    unsigned long long r;
    asm("mov.b64 %0, {%1, %2};" : "=l"(r) : "f"(a), "f"(b));
    return r;
}
static __forceinline__ __device__ void unpack2(unsigned long long v, float& a, float& b) {
    asm("mov.b64 {%0, %1}, %2;" : "=f"(a), "=f"(b) : "l"(v));
}
// Packed fp32 FMA: 2 exact fp32 FMAs per instruction (FFMA2), 2x the 3-reg FFMA rate.
static __forceinline__ __device__ unsigned long long ffma2(unsigned long long a,
                                                           unsigned long long b,
                                                           unsigned long long c) {
    unsigned long long d;
    asm("fma.rn.f32x2 %0, %1, %2, %3;" : "=l"(d) : "l"(a), "l"(b), "l"(c));
    return d;
}

__global__ __launch_bounds__(256, 2) void vq_kernel(const float* __restrict__ x,
                                                    const float* __restrict__ cb,
                                                    float* __restrict__ out) {
    // x tile, kk-major: s_x[kk*BM + r]  (32 KB)
    __shared__ float s_x[CDIM * BM];
    // c chunk, kk-major with XOR quad swizzle: logical s_c[kk][j] at quad (j>>2)^(kk>>2)  (16 KB)
    __shared__ float s_c[BK * CDIM];

    const int tid = threadIdx.x;
    const int tx = tid & 15;          // 4 codes per tx
    const int ty = tid >> 4;          // 8 rows per ty
    const int nbase = blockIdx.x * BM;
    const int b = nbase >> 10;        // image index (HW = 1024)
    const int p = nbase & 1023;       // offset within image plane
    const float* xin = x + b * (CDIM * HWDIM) + p;   // x[n][kk] = xin[kk*HW + (n - nbase)]

    // ---- load x tile (coalesced, no transpose: input is already kk-major) ----
    {
        float4* s4 = reinterpret_cast<float4*>(s_x);
        #pragma unroll
        for (int i = 0; i < 8; ++i) {
            int e = tid + i * 256;            // 2048 float4 total
            int kk = e >> 5;                  // 32 float4 per kk-row
            int r4 = e & 31;
            s4[e] = *reinterpret_cast<const float4*>(xin + kk * HWDIM + r4 * 4);
        }
    }

    float bestv[8];
    int besti[8];
    #pragma unroll
    for (int r = 0; r < 8; ++r) { bestv[r] = 3.4e38f; besti[r] = 0; }

    for (int ch = 0; ch < NCHUNK; ++ch) {
        if (ch) __syncthreads();              // protect s_c from previous chunk's readers
        // ---- load + transpose c chunk into kk-major swizzled smem ----
        {
            const float4* g4 = reinterpret_cast<const float4*>(cb + ch * BK * CDIM);
            #pragma unroll
            for (int i = 0; i < 4; ++i) {
                int e = tid + i * 256;        // 1024 float4 = BK*CDIM/4
                int j = e >> 4;               // code row within chunk (16 f4 per row)
                int kq = e & 15;              // kk quad
                float4 v = g4[e];
                int sq = (j >> 2) ^ kq;       // swizzled j-quad
                float* dst = s_c + (kq * 4) * CDIM + sq * 4 + (j & 3);
                dst[0 * CDIM] = v.x;
                dst[1 * CDIM] = v.y;
                dst[2 * CDIM] = v.z;
                dst[3 * CDIM] = v.w;
            }
        }
        __syncthreads();

        unsigned long long acc[4][4];         // [row-pair][col], f32x2 each
        #pragma unroll
        for (int rp = 0; rp < 4; ++rp)
            #pragma unroll
            for (int m = 0; m < 4; ++m) acc[rp][m] = 0ull;

        const float4* x4 = reinterpret_cast<const float4*>(s_x);
        const float4* c4 = reinterpret_cast<const float4*>(s_c);
        #pragma unroll 16
        for (int kk = 0; kk < CDIM; ++kk) {
            float4 xa = x4[kk * 32 + ty * 2];         // rows ty*8 .. ty*8+3
            float4 xb = x4[kk * 32 + ty * 2 + 1];     // rows ty*8+4 .. ty*8+7
            unsigned long long xp[4];
            xp[0] = pack2(xa.x, xa.y);
            xp[1] = pack2(xa.z, xa.w);
            xp[2] = pack2(xb.x, xb.y);
            xp[3] = pack2(xb.z, xb.w);
            float4 cv = c4[kk * 16 + (tx ^ (kk >> 2))];   // c[kk][tx*4 .. tx*4+3]
            unsigned long long c0 = pack2(cv.x, cv.x);
            unsigned long long c1 = pack2(cv.y, cv.y);
            unsigned long long c2 = pack2(cv.z, cv.z);
            unsigned long long c3 = pack2(cv.w, cv.w);
            #pragma unroll
            for (int rp = 0; rp < 4; ++rp) {
                acc[rp][0] = ffma2(xp[rp], c0, acc[rp][0]);
                acc[rp][1] = ffma2(xp[rp], c1, acc[rp][1]);
                acc[rp][2] = ffma2(xp[rp], c2, acc[rp][2]);
                acc[rp][3] = ffma2(xp[rp], c3, acc[rp][3]);
            }
        }

        // ---- running argmin update (increasing code order -> first-min semantics) ----
        #pragma unroll
        for (int m = 0; m < 4; ++m) {
            int col = ch * BK + tx * 4 + m;
            float hn = __ldg(&d_hn[col]);
            #pragma unroll
            for (int rp = 0; rp < 4; ++rp) {
                float d0, d1;
                unpack2(acc[rp][m], d0, d1);
                float s0 = hn - d0;
                float s1 = hn - d1;
                int r0 = rp * 2, r1 = rp * 2 + 1;
                if (s0 < bestv[r0]) { bestv[r0] = s0; besti[r0] = col; }
                if (s1 < bestv[r1]) { bestv[r1] = s1; besti[r1] = col; }
            }
        }
    }

    // ---- reduce across the 16 tx lanes (same rows), lower index wins ties ----
    #pragma unroll
    for (int r = 0; r < 8; ++r) {
        float v = bestv[r];
        int idx = besti[r];
        #pragma unroll
        for (int off = 8; off > 0; off >>= 1) {
            float ov = __shfl_down_sync(0xffffffffu, v, off, 16);
            int   oi = __shfl_down_sync(0xffffffffu, idx, off, 16);
            if (ov < v || (ov == v && oi < idx)) { v = ov; idx = oi; }
        }
        besti[r] = idx;
    }

    __syncthreads();                          // all compute reads of s_c done
    int* s_idx = reinterpret_cast<int*>(s_c); // reuse c smem for the 128 winning indices
    if (tx == 0) {
        #pragma unroll
        for (int r = 0; r < 8; ++r) s_idx[ty * 8 + r] = besti[r];
    }
    __syncthreads();

    // ---- epilogue: gather code vectors, write NCHW (coalesced stores) ----
    float* outp = out + b * (CDIM * HWDIM) + p;
    #pragma unroll
    for (int i = 0; i < 32; ++i) {
        int e = tid + i * 256;                // 8192 floats
        int cch = e >> 7;                     // channel
        int r = e & 127;                      // row within tile
        outp[cch * HWDIM + r] = __ldg(&cb[s_idx[r] * CDIM + cch]);
    }
}

extern "C" void kernel_launch(void* const* d_in, const int* in_sizes, int n_in,
                              void* d_out, int out_size) {
    const float* x  = (const float*)d_in[0];   // inputs  [64,64,32,32]
    const float* cb = (const float*)d_in[1];   // codebook [1024,64]
    float* out = (float*)d_out;
    hn_kernel<<<4, 256>>>(cb);
    vq_kernel<<<512, 256>>>(x, cb, out);
}